// round 4
// baseline (speedup 1.0000x reference)
#include <cuda_runtime.h>
#include <cstdint>

#define D_DIM 1024
#define K_TOP 307

// ---------------------------------------------------------------------------
// Fast-math-immune sigmoid: 1/(1+exp(-z)) with Cody-Waite reduction + poly.
// ~2-3 ulp, monotone; avoids expf being swapped for __expf under fast math.
// ---------------------------------------------------------------------------
__device__ __forceinline__ float sigmoid_acc(float z) {
    float x = -z;
    // clamp to keep 2^n scaling in normal range; tails round to 0/1 anyway
    x = fminf(fmaxf(x, -87.0f), 87.0f);
    float t = x * 1.4426950408889634f;
    float n = rintf(t);
    float r = fmaf(n, -0.693145751953125f, x);       // ln2_hi
    r = fmaf(n, -1.42860676533018687e-06f, r);       // ln2_lo
    // exp(r) = 1 + r + r^2 * P(r)   (cephes coefficients)
    float p = 1.9875691500e-4f;
    p = fmaf(p, r, 1.3981999507e-3f);
    p = fmaf(p, r, 8.3333331174e-3f);
    p = fmaf(p, r, 4.1665795894e-2f);
    p = fmaf(p, r, 1.6666665459e-1f);
    p = fmaf(p, r, 5.0000001201e-1f);
    float y = fmaf(r * r, p, r) + 1.0f;
    int   i  = (int)n;
    float sc = __int_as_float((i + 127) << 23);
    float e  = y * sc;                                // exp(-z)
    return 1.0f / (1.0f + e);
}

// ---------------------------------------------------------------------------
// Kernel A: C[n,e] = sigmoid(sum_k X[n,k]*W[e,k] + b[e]) -> S (fp32)
// 128x128x8 tile, 256 threads, 8x8 microtile, double-buffered smem.
// ---------------------------------------------------------------------------
__global__ __launch_bounds__(256, 2)
void gemm_sigmoid_kernel(const float* __restrict__ X, const float* __restrict__ W,
                         const float* __restrict__ bias, float* __restrict__ S) {
    __shared__ float As[2][8][128];
    __shared__ float Bs[2][8][128];

    const int tid  = threadIdx.x;
    const int brow = blockIdx.y << 7;
    const int bcol = blockIdx.x << 7;

    // loaders: 256 threads, each a float4: row = tid/2, k-chunk = (tid&1)*4
    const int lrow = tid >> 1;
    const int lk   = (tid & 1) << 2;
    const float* ap = X + (size_t)(brow + lrow) * D_DIM + lk;
    const float* bp = W + (size_t)(bcol + lrow) * D_DIM + lk;

    {
        float4 a4 = *(const float4*)ap;
        float4 b4 = *(const float4*)bp;
        As[0][lk + 0][lrow] = a4.x; As[0][lk + 1][lrow] = a4.y;
        As[0][lk + 2][lrow] = a4.z; As[0][lk + 3][lrow] = a4.w;
        Bs[0][lk + 0][lrow] = b4.x; Bs[0][lk + 1][lrow] = b4.y;
        Bs[0][lk + 2][lrow] = b4.z; Bs[0][lk + 3][lrow] = b4.w;
    }
    __syncthreads();

    const int ty = tid >> 4;   // 0..15
    const int tx = tid & 15;   // 0..15

    float acc[8][8];
#pragma unroll
    for (int i = 0; i < 8; i++)
#pragma unroll
        for (int j = 0; j < 8; j++) acc[i][j] = 0.0f;

    int buf = 0;
    for (int k0 = 0; k0 < D_DIM; k0 += 8) {
        float4 an, bn;
        const bool more = (k0 + 8) < D_DIM;
        if (more) {
            an = *(const float4*)(ap + k0 + 8);
            bn = *(const float4*)(bp + k0 + 8);
        }
#pragma unroll
        for (int kk = 0; kk < 8; kk++) {
            float4 a0 = *(const float4*)&As[buf][kk][(ty << 2)];
            float4 a1 = *(const float4*)&As[buf][kk][64 + (ty << 2)];
            float4 c0 = *(const float4*)&Bs[buf][kk][(tx << 2)];
            float4 c1 = *(const float4*)&Bs[buf][kk][64 + (tx << 2)];
            float ar[8] = {a0.x, a0.y, a0.z, a0.w, a1.x, a1.y, a1.z, a1.w};
            float br[8] = {c0.x, c0.y, c0.z, c0.w, c1.x, c1.y, c1.z, c1.w};
#pragma unroll
            for (int i = 0; i < 8; i++)
#pragma unroll
                for (int j = 0; j < 8; j++)
                    acc[i][j] = fmaf(ar[i], br[j], acc[i][j]);
        }
        if (more) {
            buf ^= 1;
            As[buf][lk + 0][lrow] = an.x; As[buf][lk + 1][lrow] = an.y;
            As[buf][lk + 2][lrow] = an.z; As[buf][lk + 3][lrow] = an.w;
            Bs[buf][lk + 0][lrow] = bn.x; Bs[buf][lk + 1][lrow] = bn.y;
            Bs[buf][lk + 2][lrow] = bn.z; Bs[buf][lk + 3][lrow] = bn.w;
            __syncthreads();
        }
    }

    // epilogue: + bias, sigmoid, store
    float4 bb0 = *(const float4*)&bias[bcol + (tx << 2)];
    float4 bb1 = *(const float4*)&bias[bcol + 64 + (tx << 2)];
    float bv[8] = {bb0.x, bb0.y, bb0.z, bb0.w, bb1.x, bb1.y, bb1.z, bb1.w};

#pragma unroll
    for (int i = 0; i < 8; i++) {
        const int r = brow + ((i < 4) ? ((ty << 2) + i) : (64 + (ty << 2) + i - 4));
        float4 o0, o1;
        o0.x = sigmoid_acc(acc[i][0] + bv[0]);
        o0.y = sigmoid_acc(acc[i][1] + bv[1]);
        o0.z = sigmoid_acc(acc[i][2] + bv[2]);
        o0.w = sigmoid_acc(acc[i][3] + bv[3]);
        o1.x = sigmoid_acc(acc[i][4] + bv[4]);
        o1.y = sigmoid_acc(acc[i][5] + bv[5]);
        o1.z = sigmoid_acc(acc[i][6] + bv[6]);
        o1.w = sigmoid_acc(acc[i][7] + bv[7]);
        *(float4*)&S[(size_t)r * D_DIM + bcol + (tx << 2)]      = o0;
        *(float4*)&S[(size_t)r * D_DIM + bcol + 64 + (tx << 2)] = o1;
    }
}

// ---------------------------------------------------------------------------
// Kernel B: per-row exact top-K via radix-select on the sigmoid values.
// Positive floats -> uint bit pattern preserves order. Tie-break = lowest
// index (matches jax.lax.top_k). One block (256 threads) per row; each
// thread owns 4 contiguous elements (index order preserved for the tie scan).
// ---------------------------------------------------------------------------
__global__ __launch_bounds__(256)
void topk_mask_kernel(const float* __restrict__ X, const float* __restrict__ S,
                      float* __restrict__ O) {
    const int row = blockIdx.x;
    const int t   = threadIdx.x;
    const size_t base = (size_t)row * D_DIM;

    const uint4 u = ((const uint4*)(S + base))[t];

    __shared__ int hist[256];
    __shared__ int sscan[256];
    __shared__ uint32_t sh_pref;
    __shared__ int sh_need;
    __shared__ int wsum[8];

    uint32_t prefix = 0;
    int need = K_TOP;
    const uint32_t dmask[4] = {0u, 0xFF000000u, 0xFFFF0000u, 0xFFFFFF00u};

#pragma unroll
    for (int p = 0; p < 4; p++) {
        const int shift = 24 - (p << 3);
        const uint32_t dm = dmask[p];
        hist[t] = 0;
        __syncthreads();
        if ((u.x & dm) == prefix) atomicAdd(&hist[(u.x >> shift) & 255], 1);
        if ((u.y & dm) == prefix) atomicAdd(&hist[(u.y >> shift) & 255], 1);
        if ((u.z & dm) == prefix) atomicAdd(&hist[(u.z >> shift) & 255], 1);
        if ((u.w & dm) == prefix) atomicAdd(&hist[(u.w >> shift) & 255], 1);
        __syncthreads();
        sscan[t] = hist[t];
        __syncthreads();
        // suffix (descending) inclusive scan: sscan[d] = # candidates with digit >= d
#pragma unroll
        for (int off = 1; off < 256; off <<= 1) {
            int v = (t + off < 256) ? sscan[t + off] : 0;
            __syncthreads();
            sscan[t] += v;
            __syncthreads();
        }
        const int ge  = sscan[t];
        const int nxt = (t < 255) ? sscan[t + 1] : 0;
        if (ge >= need && nxt < need) {
            sh_pref = prefix | ((uint32_t)t << shift);
            sh_need = need - nxt;
        }
        __syncthreads();
        prefix = sh_pref;
        need   = sh_need;
        __syncthreads();
    }

    const uint32_t T = prefix;  // exact K-th largest value (bit pattern)

    // index-ordered rank among elements == T
    const int e0 = (u.x == T), e1 = (u.y == T), e2 = (u.z == T), e3 = (u.w == T);
    const int cnt = e0 + e1 + e2 + e3;
    const int lane = t & 31, wid = t >> 5;
    int incl = cnt;
#pragma unroll
    for (int off = 1; off < 32; off <<= 1) {
        int v = __shfl_up_sync(0xffffffffu, incl, off);
        if (lane >= off) incl += v;
    }
    if (lane == 31) wsum[wid] = incl;
    __syncthreads();
    if (t == 0) {
        int s = 0;
#pragma unroll
        for (int i = 0; i < 8; i++) { int v = wsum[i]; wsum[i] = s; s += v; }
    }
    __syncthreads();
    int rank = wsum[wid] + (incl - cnt);  // exclusive prefix before my first elem

    const float4 xv = ((const float4*)(X + base))[t];
    float4 o;
    const bool s0 = (u.x > T) || (e0 && rank < need); rank += e0;
    const bool s1 = (u.y > T) || (e1 && rank < need); rank += e1;
    const bool s2 = (u.z > T) || (e2 && rank < need); rank += e2;
    const bool s3 = (u.w > T) || (e3 && rank < need);
    o.x = s0 ? xv.x : 0.0f;
    o.y = s1 ? xv.y : 0.0f;
    o.z = s2 ? xv.z : 0.0f;
    o.w = s3 ? xv.w : 0.0f;
    ((float4*)(O + base))[t] = o;
}

// ---------------------------------------------------------------------------
extern "C" void kernel_launch(void* const* d_in, const int* in_sizes, int n_in,
                              void* d_out, int out_size) {
    const float* X = (const float*)d_in[0];  // [N, 1024]
    const float* W = (const float*)d_in[1];  // [1024, 1024]
    const float* b = (const float*)d_in[2];  // [1024]
    float* out = (float*)d_out;              // [2, N, 1024]: (mask*x, scores)

    const int N = in_sizes[0] / D_DIM;
    float* S = out + (size_t)N * D_DIM;      // feature_scores half

    dim3 grid(D_DIM / 128, N / 128);
    gemm_sigmoid_kernel<<<grid, 256>>>(X, W, b, S);
    topk_mask_kernel<<<N, 256>>>(X, S, out);
}

// round 5
// speedup vs baseline: 1.0003x; 1.0003x over previous
#include <cuda_runtime.h>
#include <cstdint>

#define D_DIM 1024
#define K_TOP 307

// ---------------------------------------------------------------------------
// Fast-math-immune sigmoid: 1/(1+exp(-z)) with Cody-Waite reduction + poly.
// ~2-3 ulp, monotone; avoids expf being swapped for __expf under fast math.
// ---------------------------------------------------------------------------
__device__ __forceinline__ float sigmoid_acc(float z) {
    float x = -z;
    // clamp to keep 2^n scaling in normal range; tails round to 0/1 anyway
    x = fminf(fmaxf(x, -87.0f), 87.0f);
    float t = x * 1.4426950408889634f;
    float n = rintf(t);
    float r = fmaf(n, -0.693145751953125f, x);       // ln2_hi
    r = fmaf(n, -1.42860676533018687e-06f, r);       // ln2_lo
    // exp(r) = 1 + r + r^2 * P(r)   (cephes coefficients)
    float p = 1.9875691500e-4f;
    p = fmaf(p, r, 1.3981999507e-3f);
    p = fmaf(p, r, 8.3333331174e-3f);
    p = fmaf(p, r, 4.1665795894e-2f);
    p = fmaf(p, r, 1.6666665459e-1f);
    p = fmaf(p, r, 5.0000001201e-1f);
    float y = fmaf(r * r, p, r) + 1.0f;
    int   i  = (int)n;
    float sc = __int_as_float((i + 127) << 23);
    float e  = y * sc;                                // exp(-z)
    return 1.0f / (1.0f + e);
}

// ---------------------------------------------------------------------------
// Kernel A: C[n,e] = sigmoid(sum_k X[n,k]*W[e,k] + b[e]) -> S (fp32)
// 128x128x8 tile, 256 threads, 8x8 microtile, double-buffered smem.
// ---------------------------------------------------------------------------
__global__ __launch_bounds__(256, 2)
void gemm_sigmoid_kernel(const float* __restrict__ X, const float* __restrict__ W,
                         const float* __restrict__ bias, float* __restrict__ S) {
    __shared__ float As[2][8][128];
    __shared__ float Bs[2][8][128];

    const int tid  = threadIdx.x;
    const int brow = blockIdx.y << 7;
    const int bcol = blockIdx.x << 7;

    // loaders: 256 threads, each a float4: row = tid/2, k-chunk = (tid&1)*4
    const int lrow = tid >> 1;
    const int lk   = (tid & 1) << 2;
    const float* ap = X + (size_t)(brow + lrow) * D_DIM + lk;
    const float* bp = W + (size_t)(bcol + lrow) * D_DIM + lk;

    {
        float4 a4 = *(const float4*)ap;
        float4 b4 = *(const float4*)bp;
        As[0][lk + 0][lrow] = a4.x; As[0][lk + 1][lrow] = a4.y;
        As[0][lk + 2][lrow] = a4.z; As[0][lk + 3][lrow] = a4.w;
        Bs[0][lk + 0][lrow] = b4.x; Bs[0][lk + 1][lrow] = b4.y;
        Bs[0][lk + 2][lrow] = b4.z; Bs[0][lk + 3][lrow] = b4.w;
    }
    __syncthreads();

    const int ty = tid >> 4;   // 0..15
    const int tx = tid & 15;   // 0..15

    float acc[8][8];
#pragma unroll
    for (int i = 0; i < 8; i++)
#pragma unroll
        for (int j = 0; j < 8; j++) acc[i][j] = 0.0f;

    int buf = 0;
    for (int k0 = 0; k0 < D_DIM; k0 += 8) {
        float4 an, bn;
        const bool more = (k0 + 8) < D_DIM;
        if (more) {
            an = *(const float4*)(ap + k0 + 8);
            bn = *(const float4*)(bp + k0 + 8);
        }
#pragma unroll
        for (int kk = 0; kk < 8; kk++) {
            float4 a0 = *(const float4*)&As[buf][kk][(ty << 2)];
            float4 a1 = *(const float4*)&As[buf][kk][64 + (ty << 2)];
            float4 c0 = *(const float4*)&Bs[buf][kk][(tx << 2)];
            float4 c1 = *(const float4*)&Bs[buf][kk][64 + (tx << 2)];
            float ar[8] = {a0.x, a0.y, a0.z, a0.w, a1.x, a1.y, a1.z, a1.w};
            float br[8] = {c0.x, c0.y, c0.z, c0.w, c1.x, c1.y, c1.z, c1.w};
#pragma unroll
            for (int i = 0; i < 8; i++)
#pragma unroll
                for (int j = 0; j < 8; j++)
                    acc[i][j] = fmaf(ar[i], br[j], acc[i][j]);
        }
        if (more) {
            buf ^= 1;
            As[buf][lk + 0][lrow] = an.x; As[buf][lk + 1][lrow] = an.y;
            As[buf][lk + 2][lrow] = an.z; As[buf][lk + 3][lrow] = an.w;
            Bs[buf][lk + 0][lrow] = bn.x; Bs[buf][lk + 1][lrow] = bn.y;
            Bs[buf][lk + 2][lrow] = bn.z; Bs[buf][lk + 3][lrow] = bn.w;
            __syncthreads();
        }
    }

    // epilogue: + bias, sigmoid, store
    float4 bb0 = *(const float4*)&bias[bcol + (tx << 2)];
    float4 bb1 = *(const float4*)&bias[bcol + 64 + (tx << 2)];
    float bv[8] = {bb0.x, bb0.y, bb0.z, bb0.w, bb1.x, bb1.y, bb1.z, bb1.w};

#pragma unroll
    for (int i = 0; i < 8; i++) {
        const int r = brow + ((i < 4) ? ((ty << 2) + i) : (64 + (ty << 2) + i - 4));
        float4 o0, o1;
        o0.x = sigmoid_acc(acc[i][0] + bv[0]);
        o0.y = sigmoid_acc(acc[i][1] + bv[1]);
        o0.z = sigmoid_acc(acc[i][2] + bv[2]);
        o0.w = sigmoid_acc(acc[i][3] + bv[3]);
        o1.x = sigmoid_acc(acc[i][4] + bv[4]);
        o1.y = sigmoid_acc(acc[i][5] + bv[5]);
        o1.z = sigmoid_acc(acc[i][6] + bv[6]);
        o1.w = sigmoid_acc(acc[i][7] + bv[7]);
        *(float4*)&S[(size_t)r * D_DIM + bcol + (tx << 2)]      = o0;
        *(float4*)&S[(size_t)r * D_DIM + bcol + 64 + (tx << 2)] = o1;
    }
}

// ---------------------------------------------------------------------------
// Kernel B: per-row exact top-K via radix-select on the sigmoid values.
// Positive floats -> uint bit pattern preserves order. Tie-break = lowest
// index (matches jax.lax.top_k). One block (256 threads) per row; each
// thread owns 4 contiguous elements (index order preserved for the tie scan).
// ---------------------------------------------------------------------------
__global__ __launch_bounds__(256)
void topk_mask_kernel(const float* __restrict__ X, const float* __restrict__ S,
                      float* __restrict__ O) {
    const int row = blockIdx.x;
    const int t   = threadIdx.x;
    const size_t base = (size_t)row * D_DIM;

    const uint4 u = ((const uint4*)(S + base))[t];

    __shared__ int hist[256];
    __shared__ int sscan[256];
    __shared__ uint32_t sh_pref;
    __shared__ int sh_need;
    __shared__ int wsum[8];

    uint32_t prefix = 0;
    int need = K_TOP;
    const uint32_t dmask[4] = {0u, 0xFF000000u, 0xFFFF0000u, 0xFFFFFF00u};

#pragma unroll
    for (int p = 0; p < 4; p++) {
        const int shift = 24 - (p << 3);
        const uint32_t dm = dmask[p];
        hist[t] = 0;
        __syncthreads();
        if ((u.x & dm) == prefix) atomicAdd(&hist[(u.x >> shift) & 255], 1);
        if ((u.y & dm) == prefix) atomicAdd(&hist[(u.y >> shift) & 255], 1);
        if ((u.z & dm) == prefix) atomicAdd(&hist[(u.z >> shift) & 255], 1);
        if ((u.w & dm) == prefix) atomicAdd(&hist[(u.w >> shift) & 255], 1);
        __syncthreads();
        sscan[t] = hist[t];
        __syncthreads();
        // suffix (descending) inclusive scan: sscan[d] = # candidates with digit >= d
#pragma unroll
        for (int off = 1; off < 256; off <<= 1) {
            int v = (t + off < 256) ? sscan[t + off] : 0;
            __syncthreads();
            sscan[t] += v;
            __syncthreads();
        }
        const int ge  = sscan[t];
        const int nxt = (t < 255) ? sscan[t + 1] : 0;
        if (ge >= need && nxt < need) {
            sh_pref = prefix | ((uint32_t)t << shift);
            sh_need = need - nxt;
        }
        __syncthreads();
        prefix = sh_pref;
        need   = sh_need;
        __syncthreads();
    }

    const uint32_t T = prefix;  // exact K-th largest value (bit pattern)

    // index-ordered rank among elements == T
    const int e0 = (u.x == T), e1 = (u.y == T), e2 = (u.z == T), e3 = (u.w == T);
    const int cnt = e0 + e1 + e2 + e3;
    const int lane = t & 31, wid = t >> 5;
    int incl = cnt;
#pragma unroll
    for (int off = 1; off < 32; off <<= 1) {
        int v = __shfl_up_sync(0xffffffffu, incl, off);
        if (lane >= off) incl += v;
    }
    if (lane == 31) wsum[wid] = incl;
    __syncthreads();
    if (t == 0) {
        int s = 0;
#pragma unroll
        for (int i = 0; i < 8; i++) { int v = wsum[i]; wsum[i] = s; s += v; }
    }
    __syncthreads();
    int rank = wsum[wid] + (incl - cnt);  // exclusive prefix before my first elem

    const float4 xv = ((const float4*)(X + base))[t];
    float4 o;
    const bool s0 = (u.x > T) || (e0 && rank < need); rank += e0;
    const bool s1 = (u.y > T) || (e1 && rank < need); rank += e1;
    const bool s2 = (u.z > T) || (e2 && rank < need); rank += e2;
    const bool s3 = (u.w > T) || (e3 && rank < need);
    o.x = s0 ? xv.x : 0.0f;
    o.y = s1 ? xv.y : 0.0f;
    o.z = s2 ? xv.z : 0.0f;
    o.w = s3 ? xv.w : 0.0f;
    ((float4*)(O + base))[t] = o;
}

// ---------------------------------------------------------------------------
extern "C" void kernel_launch(void* const* d_in, const int* in_sizes, int n_in,
                              void* d_out, int out_size) {
    const float* X = (const float*)d_in[0];  // [N, 1024]
    const float* W = (const float*)d_in[1];  // [1024, 1024]
    const float* b = (const float*)d_in[2];  // [1024]
    float* out = (float*)d_out;              // [2, N, 1024]: (mask*x, scores)

    const int N = in_sizes[0] / D_DIM;
    float* S = out + (size_t)N * D_DIM;      // feature_scores half

    dim3 grid(D_DIM / 128, N / 128);
    gemm_sigmoid_kernel<<<grid, 256>>>(X, W, b, S);
    topk_mask_kernel<<<N, 256>>>(X, S, out);
}

// round 6
// speedup vs baseline: 1.0007x; 1.0005x over previous
#include <cuda_runtime.h>
#include <cstdint>

#define D_DIM 1024
#define K_TOP 307

// ---------------------------------------------------------------------------
// Fast-math-immune sigmoid: 1/(1+exp(-z)) with Cody-Waite reduction + poly.
// ~2-3 ulp, monotone; avoids expf being swapped for __expf under fast math.
// ---------------------------------------------------------------------------
__device__ __forceinline__ float sigmoid_acc(float z) {
    float x = -z;
    // clamp to keep 2^n scaling in normal range; tails round to 0/1 anyway
    x = fminf(fmaxf(x, -87.0f), 87.0f);
    float t = x * 1.4426950408889634f;
    float n = rintf(t);
    float r = fmaf(n, -0.693145751953125f, x);       // ln2_hi
    r = fmaf(n, -1.42860676533018687e-06f, r);       // ln2_lo
    // exp(r) = 1 + r + r^2 * P(r)   (cephes coefficients)
    float p = 1.9875691500e-4f;
    p = fmaf(p, r, 1.3981999507e-3f);
    p = fmaf(p, r, 8.3333331174e-3f);
    p = fmaf(p, r, 4.1665795894e-2f);
    p = fmaf(p, r, 1.6666665459e-1f);
    p = fmaf(p, r, 5.0000001201e-1f);
    float y = fmaf(r * r, p, r) + 1.0f;
    int   i  = (int)n;
    float sc = __int_as_float((i + 127) << 23);
    float e  = y * sc;                                // exp(-z)
    return 1.0f / (1.0f + e);
}

// ---------------------------------------------------------------------------
// Kernel A: C[n,e] = sigmoid(sum_k X[n,k]*W[e,k] + b[e]) -> S (fp32)
// 128x128x8 tile, 256 threads, 8x8 microtile, double-buffered smem.
// ---------------------------------------------------------------------------
__global__ __launch_bounds__(256, 2)
void gemm_sigmoid_kernel(const float* __restrict__ X, const float* __restrict__ W,
                         const float* __restrict__ bias, float* __restrict__ S) {
    __shared__ float As[2][8][128];
    __shared__ float Bs[2][8][128];

    const int tid  = threadIdx.x;
    const int brow = blockIdx.y << 7;
    const int bcol = blockIdx.x << 7;

    // loaders: 256 threads, each a float4: row = tid/2, k-chunk = (tid&1)*4
    const int lrow = tid >> 1;
    const int lk   = (tid & 1) << 2;
    const float* ap = X + (size_t)(brow + lrow) * D_DIM + lk;
    const float* bp = W + (size_t)(bcol + lrow) * D_DIM + lk;

    {
        float4 a4 = *(const float4*)ap;
        float4 b4 = *(const float4*)bp;
        As[0][lk + 0][lrow] = a4.x; As[0][lk + 1][lrow] = a4.y;
        As[0][lk + 2][lrow] = a4.z; As[0][lk + 3][lrow] = a4.w;
        Bs[0][lk + 0][lrow] = b4.x; Bs[0][lk + 1][lrow] = b4.y;
        Bs[0][lk + 2][lrow] = b4.z; Bs[0][lk + 3][lrow] = b4.w;
    }
    __syncthreads();

    const int ty = tid >> 4;   // 0..15
    const int tx = tid & 15;   // 0..15

    float acc[8][8];
#pragma unroll
    for (int i = 0; i < 8; i++)
#pragma unroll
        for (int j = 0; j < 8; j++) acc[i][j] = 0.0f;

    int buf = 0;
    for (int k0 = 0; k0 < D_DIM; k0 += 8) {
        float4 an, bn;
        const bool more = (k0 + 8) < D_DIM;
        if (more) {
            an = *(const float4*)(ap + k0 + 8);
            bn = *(const float4*)(bp + k0 + 8);
        }
#pragma unroll
        for (int kk = 0; kk < 8; kk++) {
            float4 a0 = *(const float4*)&As[buf][kk][(ty << 2)];
            float4 a1 = *(const float4*)&As[buf][kk][64 + (ty << 2)];
            float4 c0 = *(const float4*)&Bs[buf][kk][(tx << 2)];
            float4 c1 = *(const float4*)&Bs[buf][kk][64 + (tx << 2)];
            float ar[8] = {a0.x, a0.y, a0.z, a0.w, a1.x, a1.y, a1.z, a1.w};
            float br[8] = {c0.x, c0.y, c0.z, c0.w, c1.x, c1.y, c1.z, c1.w};
#pragma unroll
            for (int i = 0; i < 8; i++)
#pragma unroll
                for (int j = 0; j < 8; j++)
                    acc[i][j] = fmaf(ar[i], br[j], acc[i][j]);
        }
        if (more) {
            buf ^= 1;
            As[buf][lk + 0][lrow] = an.x; As[buf][lk + 1][lrow] = an.y;
            As[buf][lk + 2][lrow] = an.z; As[buf][lk + 3][lrow] = an.w;
            Bs[buf][lk + 0][lrow] = bn.x; Bs[buf][lk + 1][lrow] = bn.y;
            Bs[buf][lk + 2][lrow] = bn.z; Bs[buf][lk + 3][lrow] = bn.w;
            __syncthreads();
        }
    }

    // epilogue: + bias, sigmoid, store
    float4 bb0 = *(const float4*)&bias[bcol + (tx << 2)];
    float4 bb1 = *(const float4*)&bias[bcol + 64 + (tx << 2)];
    float bv[8] = {bb0.x, bb0.y, bb0.z, bb0.w, bb1.x, bb1.y, bb1.z, bb1.w};

#pragma unroll
    for (int i = 0; i < 8; i++) {
        const int r = brow + ((i < 4) ? ((ty << 2) + i) : (64 + (ty << 2) + i - 4));
        float4 o0, o1;
        o0.x = sigmoid_acc(acc[i][0] + bv[0]);
        o0.y = sigmoid_acc(acc[i][1] + bv[1]);
        o0.z = sigmoid_acc(acc[i][2] + bv[2]);
        o0.w = sigmoid_acc(acc[i][3] + bv[3]);
        o1.x = sigmoid_acc(acc[i][4] + bv[4]);
        o1.y = sigmoid_acc(acc[i][5] + bv[5]);
        o1.z = sigmoid_acc(acc[i][6] + bv[6]);
        o1.w = sigmoid_acc(acc[i][7] + bv[7]);
        *(float4*)&S[(size_t)r * D_DIM + bcol + (tx << 2)]      = o0;
        *(float4*)&S[(size_t)r * D_DIM + bcol + 64 + (tx << 2)] = o1;
    }
}

// ---------------------------------------------------------------------------
// Kernel B: per-row exact top-K via radix-select on the sigmoid values.
// Positive floats -> uint bit pattern preserves order. Tie-break = lowest
// index (matches jax.lax.top_k). One block (256 threads) per row; each
// thread owns 4 contiguous elements (index order preserved for the tie scan).
// ---------------------------------------------------------------------------
__global__ __launch_bounds__(256)
void topk_mask_kernel(const float* __restrict__ X, const float* __restrict__ S,
                      float* __restrict__ O) {
    const int row = blockIdx.x;
    const int t   = threadIdx.x;
    const size_t base = (size_t)row * D_DIM;

    const uint4 u = ((const uint4*)(S + base))[t];

    __shared__ int hist[256];
    __shared__ int sscan[256];
    __shared__ uint32_t sh_pref;
    __shared__ int sh_need;
    __shared__ int wsum[8];

    uint32_t prefix = 0;
    int need = K_TOP;
    const uint32_t dmask[4] = {0u, 0xFF000000u, 0xFFFF0000u, 0xFFFFFF00u};

#pragma unroll
    for (int p = 0; p < 4; p++) {
        const int shift = 24 - (p << 3);
        const uint32_t dm = dmask[p];
        hist[t] = 0;
        __syncthreads();
        if ((u.x & dm) == prefix) atomicAdd(&hist[(u.x >> shift) & 255], 1);
        if ((u.y & dm) == prefix) atomicAdd(&hist[(u.y >> shift) & 255], 1);
        if ((u.z & dm) == prefix) atomicAdd(&hist[(u.z >> shift) & 255], 1);
        if ((u.w & dm) == prefix) atomicAdd(&hist[(u.w >> shift) & 255], 1);
        __syncthreads();
        sscan[t] = hist[t];
        __syncthreads();
        // suffix (descending) inclusive scan: sscan[d] = # candidates with digit >= d
#pragma unroll
        for (int off = 1; off < 256; off <<= 1) {
            int v = (t + off < 256) ? sscan[t + off] : 0;
            __syncthreads();
            sscan[t] += v;
            __syncthreads();
        }
        const int ge  = sscan[t];
        const int nxt = (t < 255) ? sscan[t + 1] : 0;
        if (ge >= need && nxt < need) {
            sh_pref = prefix | ((uint32_t)t << shift);
            sh_need = need - nxt;
        }
        __syncthreads();
        prefix = sh_pref;
        need   = sh_need;
        __syncthreads();
    }

    const uint32_t T = prefix;  // exact K-th largest value (bit pattern)

    // index-ordered rank among elements == T
    const int e0 = (u.x == T), e1 = (u.y == T), e2 = (u.z == T), e3 = (u.w == T);
    const int cnt = e0 + e1 + e2 + e3;
    const int lane = t & 31, wid = t >> 5;
    int incl = cnt;
#pragma unroll
    for (int off = 1; off < 32; off <<= 1) {
        int v = __shfl_up_sync(0xffffffffu, incl, off);
        if (lane >= off) incl += v;
    }
    if (lane == 31) wsum[wid] = incl;
    __syncthreads();
    if (t == 0) {
        int s = 0;
#pragma unroll
        for (int i = 0; i < 8; i++) { int v = wsum[i]; wsum[i] = s; s += v; }
    }
    __syncthreads();
    int rank = wsum[wid] + (incl - cnt);  // exclusive prefix before my first elem

    const float4 xv = ((const float4*)(X + base))[t];
    float4 o;
    const bool s0 = (u.x > T) || (e0 && rank < need); rank += e0;
    const bool s1 = (u.y > T) || (e1 && rank < need); rank += e1;
    const bool s2 = (u.z > T) || (e2 && rank < need); rank += e2;
    const bool s3 = (u.w > T) || (e3 && rank < need);
    o.x = s0 ? xv.x : 0.0f;
    o.y = s1 ? xv.y : 0.0f;
    o.z = s2 ? xv.z : 0.0f;
    o.w = s3 ? xv.w : 0.0f;
    ((float4*)(O + base))[t] = o;
}

// ---------------------------------------------------------------------------
extern "C" void kernel_launch(void* const* d_in, const int* in_sizes, int n_in,
                              void* d_out, int out_size) {
    const float* X = (const float*)d_in[0];  // [N, 1024]
    const float* W = (const float*)d_in[1];  // [1024, 1024]
    const float* b = (const float*)d_in[2];  // [1024]
    float* out = (float*)d_out;              // [2, N, 1024]: (mask*x, scores)

    const int N = in_sizes[0] / D_DIM;
    float* S = out + (size_t)N * D_DIM;      // feature_scores half

    dim3 grid(D_DIM / 128, N / 128);
    gemm_sigmoid_kernel<<<grid, 256>>>(X, W, b, S);
    topk_mask_kernel<<<N, 256>>>(X, S, out);
}

// round 9
// speedup vs baseline: 1.1839x; 1.1830x over previous
#include <cuda_runtime.h>
#include <cuda_bf16.h>
#include <cstdint>

#define D_DIM 1024
#define K_TOP 307
#define MAX_N 65536

// ============================ PTX helpers ===================================
__device__ __forceinline__ uint32_t smem_u32(const void* p) {
    uint32_t a;
    asm("{ .reg .u64 t; cvta.to.shared.u64 t, %1; cvt.u32.u64 %0, t; }" : "=r"(a) : "l"(p));
    return a;
}
#define CPA16(saddr, gptr) \
    asm volatile("cp.async.cg.shared.global [%0], [%1], 16;" :: "r"(saddr), "l"(gptr) : "memory")
#define CP_COMMIT() asm volatile("cp.async.commit_group;" ::: "memory")
#define CP_WAIT1()  asm volatile("cp.async.wait_group 1;" ::: "memory")
#define CP_WAIT0()  asm volatile("cp.async.wait_group 0;" ::: "memory")

#define LDSM_X4(r0, r1, r2, r3, addr) \
    asm volatile("ldmatrix.sync.aligned.m8n8.x4.shared.b16 {%0,%1,%2,%3}, [%4];" \
        : "=r"(r0), "=r"(r1), "=r"(r2), "=r"(r3) : "r"(addr))

#define MMA16816(d, a, b0, b1) \
    asm volatile("mma.sync.aligned.m16n8k16.row.col.f32.bf16.bf16.f32 " \
        "{%0,%1,%2,%3}, {%4,%5,%6,%7}, {%8,%9}, {%0,%1,%2,%3};" \
        : "+f"((d)[0]), "+f"((d)[1]), "+f"((d)[2]), "+f"((d)[3]) \
        : "r"((a)[0]), "r"((a)[1]), "r"((a)[2]), "r"((a)[3]), "r"(b0), "r"(b1))

// ============================ numeric helpers ================================
__device__ __forceinline__ float sigmoid_acc(float z) {
    float x = -z;
    x = fminf(fmaxf(x, -87.0f), 87.0f);
    float t = x * 1.4426950408889634f;
    float n = rintf(t);
    float r = fmaf(n, -0.693145751953125f, x);
    r = fmaf(n, -1.42860676533018687e-06f, r);
    float p = 1.9875691500e-4f;
    p = fmaf(p, r, 1.3981999507e-3f);
    p = fmaf(p, r, 8.3333331174e-3f);
    p = fmaf(p, r, 4.1665795894e-2f);
    p = fmaf(p, r, 1.6666665459e-1f);
    p = fmaf(p, r, 5.0000001201e-1f);
    float y = fmaf(r * r, p, r) + 1.0f;
    int   i  = (int)n;
    float sc = __int_as_float((i + 127) << 23);
    return 1.0f / (1.0f + y * sc);
}
__device__ __forceinline__ uint32_t bf16_rn(float x, float& xf) {
    uint32_t b = __float_as_uint(x);
    uint32_t r = (b + 0x7FFFu + ((b >> 16) & 1u)) & 0xFFFF0000u;
    xf = __uint_as_float(r);
    return r >> 16;
}
__device__ __forceinline__ void split3(float x, uint32_t& h, uint32_t& m, uint32_t& l) {
    float hf, mf, lf;
    h = bf16_rn(x, hf);
    float r1 = x - hf;
    m = bf16_rn(r1, mf);
    float r2 = r1 - mf;
    l = bf16_rn(r2, lf);
}

// ============================ pre-split storage ==============================
__device__ __align__(16) uint16_t g_Wh[D_DIM * D_DIM];
__device__ __align__(16) uint16_t g_Wm[D_DIM * D_DIM];
__device__ __align__(16) uint16_t g_Wl[D_DIM * D_DIM];
__device__ __align__(16) uint16_t g_Xh[(size_t)MAX_N * D_DIM];
__device__ __align__(16) uint16_t g_Xm[(size_t)MAX_N * D_DIM];
__device__ __align__(16) uint16_t g_Xl[(size_t)MAX_N * D_DIM];

__global__ __launch_bounds__(256)
void split_kernel(const float* __restrict__ src, uint16_t* __restrict__ oh,
                  uint16_t* __restrict__ om, uint16_t* __restrict__ ol) {
    size_t gid = (size_t)blockIdx.x * 256 + threadIdx.x;  // one 8-float group
    float4 a = ((const float4*)src)[2 * gid];
    float4 c = ((const float4*)src)[2 * gid + 1];
    float v[8] = {a.x, a.y, a.z, a.w, c.x, c.y, c.z, c.w};
    uint32_t h[8], m[8], l[8];
#pragma unroll
    for (int i = 0; i < 8; i++) split3(v[i], h[i], m[i], l[i]);
    uint4 H = {h[0] | (h[1] << 16), h[2] | (h[3] << 16), h[4] | (h[5] << 16), h[6] | (h[7] << 16)};
    uint4 M = {m[0] | (m[1] << 16), m[2] | (m[3] << 16), m[4] | (m[5] << 16), m[6] | (m[7] << 16)};
    uint4 L = {l[0] | (l[1] << 16), l[2] | (l[3] << 16), l[4] | (l[5] << 16), l[6] | (l[7] << 16)};
    ((uint4*)oh)[gid] = H;
    ((uint4*)om)[gid] = M;
    ((uint4*)ol)[gid] = L;
}

// ============================ GEMM (HMMA mma.sync) ===========================
// CTA tile 64(M) x 128(N), K chunks of 64. 6 bf16 products:
//   hH -> per-chunk acc_hi (zeroed each chunk, folded into fp32 total via RN)
//   hM, mH, mM, hL, lH -> persistent acc_lo (small magnitude -> bias negligible)
#define ATILE   8192                    // 64 x 64 bf16
#define BTILE   16384                   // 128 x 64 bf16
#define BOFF    (3 * ATILE)             // 24576
#define STAGE_B (3 * ATILE + 3 * BTILE) // 73728
#define SMEM_GEMM (2 * STAGE_B)         // 147456
#define NCHUNK  (D_DIM / 64)            // 16

__global__ __launch_bounds__(256, 1)
void gemm_hmma_kernel(const float* __restrict__ bias, float* __restrict__ S) {
    extern __shared__ char smem[];
    const uint32_t sb = smem_u32(smem);
    const int tid  = threadIdx.x;
    const int lane = tid & 31;
    const int wid  = tid >> 5;
    const int mg   = wid >> 2;          // 0..1 : rows mg*32..+32
    const int ng   = wid & 3;           // 0..3 : cols ng*32..+32
    const int brow = blockIdx.y << 6;   // 64-row tile
    const int bcol = blockIdx.x << 7;   // 128-col tile

#define ISSUE_STAGE(c, s)                                                     \
    do {                                                                      \
        const int k0_ = (c) * 64;                                             \
        const uint32_t st_ = sb + (s) * STAGE_B;                              \
        _Pragma("unroll")                                                     \
        for (int j = 0; j < 2; j++) {                                         \
            int g = tid + j * 256;                                            \
            int row = g >> 3, cc = g & 7;                                     \
            uint32_t sw = (uint32_t)(row * 128 + ((cc ^ (row & 7)) << 4));    \
            size_t ga = (size_t)(brow + row) * D_DIM + k0_ + cc * 8;          \
            CPA16(st_ + 0 * ATILE + sw, g_Xh + ga);                           \
            CPA16(st_ + 1 * ATILE + sw, g_Xm + ga);                           \
            CPA16(st_ + 2 * ATILE + sw, g_Xl + ga);                           \
        }                                                                     \
        _Pragma("unroll")                                                     \
        for (int j = 0; j < 4; j++) {                                         \
            int g = tid + j * 256;                                            \
            int row = g >> 3, cc = g & 7;                                     \
            uint32_t sw = (uint32_t)(row * 128 + ((cc ^ (row & 7)) << 4));    \
            size_t gb = (size_t)(bcol + row) * D_DIM + k0_ + cc * 8;          \
            CPA16(st_ + BOFF + 0 * BTILE + sw, g_Wh + gb);                    \
            CPA16(st_ + BOFF + 1 * BTILE + sw, g_Wm + gb);                    \
            CPA16(st_ + BOFF + 2 * BTILE + sw, g_Wl + gb);                    \
        }                                                                     \
        CP_COMMIT();                                                          \
    } while (0)

    // ---- ldmatrix lane addressing (validated in round 8) ----
    const int aRow = mg * 32 + (((lane >> 3) & 1) << 3) + (lane & 7);   // <64
    const int aC   = (lane >> 4);
    const uint32_t aRB = (uint32_t)(aRow * 128);
    const int aXor = aRow & 7;
    const int bRow = ng * 32 + (((lane >> 4) & 1) << 3) + (lane & 7);   // <128
    const int bC   = (lane >> 3) & 1;
    const uint32_t bRB = (uint32_t)(bRow * 128);
    const int bXor = bRow & 7;

    float tot[2][4][4];   // fp32 total of hH chunks (RN folds)
    float ah[2][4][4];    // per-chunk hH accumulator
    float al[2][4][4];    // persistent small-product accumulator
#pragma unroll
    for (int mt = 0; mt < 2; mt++)
#pragma unroll
        for (int nt = 0; nt < 4; nt++)
#pragma unroll
            for (int e = 0; e < 4; e++) { tot[mt][nt][e] = 0.0f; al[mt][nt][e] = 0.0f; }

    ISSUE_STAGE(0, 0);

    for (int c = 0; c < NCHUNK; ++c) {
        if (c + 1 < NCHUNK) {
            ISSUE_STAGE(c + 1, (c + 1) & 1);
            CP_WAIT1();
        } else {
            CP_WAIT0();
        }
        __syncthreads();

        const uint32_t stA = sb + (c & 1) * STAGE_B;
        const uint32_t stB = stA + BOFF;

        // zero the per-chunk hH accumulator
#pragma unroll
        for (int mt = 0; mt < 2; mt++)
#pragma unroll
            for (int nt = 0; nt < 4; nt++)
#pragma unroll
                for (int e = 0; e < 4; e++) ah[mt][nt][e] = 0.0f;

#pragma unroll
        for (int ks = 0; ks < 4; ++ks) {
            uint32_t a[3][2][4];
            uint32_t b[3][2][4];
#pragma unroll
            for (int s = 0; s < 3; s++) {
#pragma unroll
                for (int mt = 0; mt < 2; mt++) {
                    uint32_t addr = stA + s * ATILE + aRB + mt * 2048 +
                                    (uint32_t)(((aC + 2 * ks) ^ aXor) << 4);
                    LDSM_X4(a[s][mt][0], a[s][mt][1], a[s][mt][2], a[s][mt][3], addr);
                }
#pragma unroll
                for (int np = 0; np < 2; np++) {
                    uint32_t addr = stB + s * BTILE + bRB + np * 2048 +
                                    (uint32_t)(((bC + 2 * ks) ^ bXor) << 4);
                    LDSM_X4(b[s][np][0], b[s][np][1], b[s][np][2], b[s][np][3], addr);
                }
            }
            // products: p0 = hH -> ah; p1..p5 = hM, mH, mM, hL, lH -> al
            const int SA[6] = {0, 0, 1, 1, 0, 2};
            const int SB[6] = {0, 1, 0, 1, 2, 0};
#pragma unroll
            for (int p = 0; p < 6; p++) {
#pragma unroll
                for (int mt = 0; mt < 2; mt++) {
#pragma unroll
                    for (int np = 0; np < 2; np++) {
                        if (p == 0) {
                            MMA16816(ah[mt][2 * np + 0], a[SA[p]][mt],
                                     b[SB[p]][np][0], b[SB[p]][np][1]);
                            MMA16816(ah[mt][2 * np + 1], a[SA[p]][mt],
                                     b[SB[p]][np][2], b[SB[p]][np][3]);
                        } else {
                            MMA16816(al[mt][2 * np + 0], a[SA[p]][mt],
                                     b[SB[p]][np][0], b[SB[p]][np][1]);
                            MMA16816(al[mt][2 * np + 1], a[SA[p]][mt],
                                     b[SB[p]][np][2], b[SB[p]][np][3]);
                        }
                    }
                }
            }
        }
        // RN fold of the chunk's hH partial into the fp32 total
#pragma unroll
        for (int mt = 0; mt < 2; mt++)
#pragma unroll
            for (int nt = 0; nt < 4; nt++)
#pragma unroll
                for (int e = 0; e < 4; e++) tot[mt][nt][e] += ah[mt][nt][e];
        __syncthreads();
    }

    // ---- epilogue: total + small + bias -> sigmoid, float2 stores ----
#pragma unroll
    for (int mt = 0; mt < 2; mt++) {
        const int m0 = brow + mg * 32 + mt * 16 + (lane >> 2);
#pragma unroll
        for (int nt = 0; nt < 4; nt++) {
            const int n0 = bcol + ng * 32 + nt * 8 + 2 * (lane & 3);
            const float2 bb = *(const float2*)&bias[n0];
            float2 o0, o1;
            o0.x = sigmoid_acc((tot[mt][nt][0] + al[mt][nt][0]) + bb.x);
            o0.y = sigmoid_acc((tot[mt][nt][1] + al[mt][nt][1]) + bb.y);
            o1.x = sigmoid_acc((tot[mt][nt][2] + al[mt][nt][2]) + bb.x);
            o1.y = sigmoid_acc((tot[mt][nt][3] + al[mt][nt][3]) + bb.y);
            *(float2*)&S[(size_t)m0 * D_DIM + n0]       = o0;
            *(float2*)&S[(size_t)(m0 + 8) * D_DIM + n0] = o1;
        }
    }
}

// ============================ top-k mask =====================================
__global__ __launch_bounds__(256)
void topk_mask_kernel(const float* __restrict__ X, const float* __restrict__ S,
                      float* __restrict__ O) {
    const int row = blockIdx.x;
    const int t   = threadIdx.x;
    const size_t base = (size_t)row * D_DIM;

    const uint4 u = ((const uint4*)(S + base))[t];

    __shared__ int hist[256];
    __shared__ int sscan[256];
    __shared__ uint32_t sh_pref;
    __shared__ int sh_need;
    __shared__ int wsum[8];

    uint32_t prefix = 0;
    int need = K_TOP;
    const uint32_t dmask[4] = {0u, 0xFF000000u, 0xFFFF0000u, 0xFFFFFF00u};

#pragma unroll
    for (int p = 0; p < 4; p++) {
        const int shift = 24 - (p << 3);
        const uint32_t dm = dmask[p];
        hist[t] = 0;
        __syncthreads();
        if ((u.x & dm) == prefix) atomicAdd(&hist[(u.x >> shift) & 255], 1);
        if ((u.y & dm) == prefix) atomicAdd(&hist[(u.y >> shift) & 255], 1);
        if ((u.z & dm) == prefix) atomicAdd(&hist[(u.z >> shift) & 255], 1);
        if ((u.w & dm) == prefix) atomicAdd(&hist[(u.w >> shift) & 255], 1);
        __syncthreads();
        sscan[t] = hist[t];
        __syncthreads();
#pragma unroll
        for (int off = 1; off < 256; off <<= 1) {
            int v = (t + off < 256) ? sscan[t + off] : 0;
            __syncthreads();
            sscan[t] += v;
            __syncthreads();
        }
        const int ge  = sscan[t];
        const int nxt = (t < 255) ? sscan[t + 1] : 0;
        if (ge >= need && nxt < need) {
            sh_pref = prefix | ((uint32_t)t << shift);
            sh_need = need - nxt;
        }
        __syncthreads();
        prefix = sh_pref;
        need   = sh_need;
        __syncthreads();
    }

    const uint32_t T = prefix;

    const int e0 = (u.x == T), e1 = (u.y == T), e2 = (u.z == T), e3 = (u.w == T);
    const int cnt = e0 + e1 + e2 + e3;
    const int lane = t & 31, wid = t >> 5;
    int incl = cnt;
#pragma unroll
    for (int off = 1; off < 32; off <<= 1) {
        int v = __shfl_up_sync(0xffffffffu, incl, off);
        if (lane >= off) incl += v;
    }
    if (lane == 31) wsum[wid] = incl;
    __syncthreads();
    if (t == 0) {
        int ssum = 0;
#pragma unroll
        for (int i = 0; i < 8; i++) { int v = wsum[i]; wsum[i] = ssum; ssum += v; }
    }
    __syncthreads();
    int rank = wsum[wid] + (incl - cnt);

    const float4 xv = ((const float4*)(X + base))[t];
    float4 o;
    const bool s0 = (u.x > T) || (e0 && rank < need); rank += e0;
    const bool s1 = (u.y > T) || (e1 && rank < need); rank += e1;
    const bool s2 = (u.z > T) || (e2 && rank < need); rank += e2;
    const bool s3 = (u.w > T) || (e3 && rank < need);
    o.x = s0 ? xv.x : 0.0f;
    o.y = s1 ? xv.y : 0.0f;
    o.z = s2 ? xv.z : 0.0f;
    o.w = s3 ? xv.w : 0.0f;
    ((float4*)(O + base))[t] = o;
}

// ============================ launch =========================================
extern "C" void kernel_launch(void* const* d_in, const int* in_sizes, int n_in,
                              void* d_out, int out_size) {
    const float* X = (const float*)d_in[0];  // [N, 1024]
    const float* W = (const float*)d_in[1];  // [1024, 1024]
    const float* b = (const float*)d_in[2];  // [1024]
    float* out = (float*)d_out;              // [2, N, 1024]

    const int N = in_sizes[0] / D_DIM;
    float* S = out + (size_t)N * D_DIM;

    uint16_t *wh, *wm, *wl, *xh, *xm, *xl;
    cudaGetSymbolAddress((void**)&wh, g_Wh);
    cudaGetSymbolAddress((void**)&wm, g_Wm);
    cudaGetSymbolAddress((void**)&wl, g_Wl);
    cudaGetSymbolAddress((void**)&xh, g_Xh);
    cudaGetSymbolAddress((void**)&xm, g_Xm);
    cudaGetSymbolAddress((void**)&xl, g_Xl);

    cudaFuncSetAttribute(gemm_hmma_kernel,
                         cudaFuncAttributeMaxDynamicSharedMemorySize, SMEM_GEMM);

    split_kernel<<<D_DIM * D_DIM / 8 / 256, 256>>>(W, wh, wm, wl);
    split_kernel<<<(int)((size_t)N * D_DIM / 8 / 256), 256>>>(X, xh, xm, xl);
    gemm_hmma_kernel<<<dim3(D_DIM / 128, N / 64), 256, SMEM_GEMM>>>(b, S);
    topk_mask_kernel<<<N, 256>>>(X, S, out);
}

// round 10
// speedup vs baseline: 1.8648x; 1.5752x over previous
#include <cuda_runtime.h>
#include <cuda_fp16.h>
#include <cstdint>

#define D_DIM 1024
#define K_TOP 307
#define MAX_N 65536

// ============================ PTX helpers ===================================
__device__ __forceinline__ uint32_t smem_u32(const void* p) {
    uint32_t a;
    asm("{ .reg .u64 t; cvta.to.shared.u64 t, %1; cvt.u32.u64 %0, t; }" : "=r"(a) : "l"(p));
    return a;
}
#define CPA16(saddr, gptr) \
    asm volatile("cp.async.cg.shared.global [%0], [%1], 16;" :: "r"(saddr), "l"(gptr) : "memory")
#define CP_COMMIT() asm volatile("cp.async.commit_group;" ::: "memory")
#define CP_WAIT1()  asm volatile("cp.async.wait_group 1;" ::: "memory")
#define CP_WAIT0()  asm volatile("cp.async.wait_group 0;" ::: "memory")

#define LDSM_X4(r0, r1, r2, r3, addr) \
    asm volatile("ldmatrix.sync.aligned.m8n8.x4.shared.b16 {%0,%1,%2,%3}, [%4];" \
        : "=r"(r0), "=r"(r1), "=r"(r2), "=r"(r3) : "r"(addr))

#define MMA16816F16(d, a, b0, b1) \
    asm volatile("mma.sync.aligned.m16n8k16.row.col.f32.f16.f16.f32 " \
        "{%0,%1,%2,%3}, {%4,%5,%6,%7}, {%8,%9}, {%0,%1,%2,%3};" \
        : "+f"((d)[0]), "+f"((d)[1]), "+f"((d)[2]), "+f"((d)[3]) \
        : "r"((a)[0]), "r"((a)[1]), "r"((a)[2]), "r"((a)[3]), "r"(b0), "r"(b1))

// ============================ numeric helpers ================================
__device__ __forceinline__ float sigmoid_acc(float z) {
    float x = -z;
    x = fminf(fmaxf(x, -87.0f), 87.0f);
    float t = x * 1.4426950408889634f;
    float n = rintf(t);
    float r = fmaf(n, -0.693145751953125f, x);
    r = fmaf(n, -1.42860676533018687e-06f, r);
    float p = 1.9875691500e-4f;
    p = fmaf(p, r, 1.3981999507e-3f);
    p = fmaf(p, r, 8.3333331174e-3f);
    p = fmaf(p, r, 4.1665795894e-2f);
    p = fmaf(p, r, 1.6666665459e-1f);
    p = fmaf(p, r, 5.0000001201e-1f);
    float y = fmaf(r * r, p, r) + 1.0f;
    int   i  = (int)n;
    float sc = __int_as_float((i + 127) << 23);
    return 1.0f / (1.0f + y * sc);
}

// fp16 2-way split: x = h + m * 2^-11  (m stored pre-scaled by 2048, normal range)
__device__ __forceinline__ void split2h(float x, uint16_t& h, uint16_t& m) {
    __half hh = __float2half_rn(x);
    float  hf = __half2float(hh);
    __half mh = __float2half_rn((x - hf) * 2048.0f);
    h = __half_as_ushort(hh);
    m = __half_as_ushort(mh);
}

// ============================ pre-split storage ==============================
__device__ __align__(16) uint16_t g_Wh[D_DIM * D_DIM];
__device__ __align__(16) uint16_t g_Wm[D_DIM * D_DIM];
__device__ __align__(16) uint16_t g_Xh[(size_t)MAX_N * D_DIM];
__device__ __align__(16) uint16_t g_Xm[(size_t)MAX_N * D_DIM];

__global__ __launch_bounds__(256)
void split2_kernel(const float* __restrict__ src, uint16_t* __restrict__ oh,
                   uint16_t* __restrict__ om) {
    size_t gid = (size_t)blockIdx.x * 256 + threadIdx.x;  // one 8-float group
    float4 a = ((const float4*)src)[2 * gid];
    float4 c = ((const float4*)src)[2 * gid + 1];
    float v[8] = {a.x, a.y, a.z, a.w, c.x, c.y, c.z, c.w};
    uint16_t h[8], m[8];
#pragma unroll
    for (int i = 0; i < 8; i++) split2h(v[i], h[i], m[i]);
    uint4 H = {(uint32_t)h[0] | ((uint32_t)h[1] << 16), (uint32_t)h[2] | ((uint32_t)h[3] << 16),
               (uint32_t)h[4] | ((uint32_t)h[5] << 16), (uint32_t)h[6] | ((uint32_t)h[7] << 16)};
    uint4 M = {(uint32_t)m[0] | ((uint32_t)m[1] << 16), (uint32_t)m[2] | ((uint32_t)m[3] << 16),
               (uint32_t)m[4] | ((uint32_t)m[5] << 16), (uint32_t)m[6] | ((uint32_t)m[7] << 16)};
    ((uint4*)oh)[gid] = H;
    ((uint4*)om)[gid] = M;
}

// ============================ GEMM (HMMA fp16 mma.sync) ======================
// CTA tile 64(M) x 128(N), K chunks of 64. 3 fp16 products:
//   hH -> per-chunk accumulator ah (zeroed each chunk, RN-folded into tot)
//   hM' + m'H -> persistent accumulator al, scaled by 2^-11 at epilogue
#define ATILE   8192                    // 64 x 64 fp16
#define BTILE   16384                   // 128 x 64 fp16
#define BOFF    (2 * ATILE)             // 16384
#define STAGE_B (2 * ATILE + 2 * BTILE) // 49152
#define SMEM_GEMM (2 * STAGE_B)         // 98304
#define NCHUNK  (D_DIM / 64)            // 16

__global__ __launch_bounds__(256, 1)
void gemm_hmma_kernel(const float* __restrict__ bias, float* __restrict__ S) {
    extern __shared__ char smem[];
    const uint32_t sb = smem_u32(smem);
    const int tid  = threadIdx.x;
    const int lane = tid & 31;
    const int wid  = tid >> 5;
    const int mg   = wid >> 2;          // 0..1 : rows mg*32..+32
    const int ng   = wid & 3;           // 0..3 : cols ng*32..+32
    const int brow = blockIdx.y << 6;   // 64-row tile
    const int bcol = blockIdx.x << 7;   // 128-col tile

#define ISSUE_STAGE(c, s)                                                     \
    do {                                                                      \
        const int k0_ = (c) * 64;                                             \
        const uint32_t st_ = sb + (s) * STAGE_B;                              \
        _Pragma("unroll")                                                     \
        for (int j = 0; j < 2; j++) {                                         \
            int g = tid + j * 256;                                            \
            int row = g >> 3, cc = g & 7;                                     \
            uint32_t sw = (uint32_t)(row * 128 + ((cc ^ (row & 7)) << 4));    \
            size_t ga = (size_t)(brow + row) * D_DIM + k0_ + cc * 8;          \
            CPA16(st_ + 0 * ATILE + sw, g_Xh + ga);                           \
            CPA16(st_ + 1 * ATILE + sw, g_Xm + ga);                           \
        }                                                                     \
        _Pragma("unroll")                                                     \
        for (int j = 0; j < 4; j++) {                                         \
            int g = tid + j * 256;                                            \
            int row = g >> 3, cc = g & 7;                                     \
            uint32_t sw = (uint32_t)(row * 128 + ((cc ^ (row & 7)) << 4));    \
            size_t gb = (size_t)(bcol + row) * D_DIM + k0_ + cc * 8;          \
            CPA16(st_ + BOFF + 0 * BTILE + sw, g_Wh + gb);                    \
            CPA16(st_ + BOFF + 1 * BTILE + sw, g_Wm + gb);                    \
        }                                                                     \
        CP_COMMIT();                                                          \
    } while (0)

    // ---- ldmatrix lane addressing (validated in rounds 8/9) ----
    const int aRow = mg * 32 + (((lane >> 3) & 1) << 3) + (lane & 7);   // <64
    const int aC   = (lane >> 4);
    const uint32_t aRB = (uint32_t)(aRow * 128);
    const int aXor = aRow & 7;
    const int bRow = ng * 32 + (((lane >> 4) & 1) << 3) + (lane & 7);   // <128
    const int bC   = (lane >> 3) & 1;
    const uint32_t bRB = (uint32_t)(bRow * 128);
    const int bXor = bRow & 7;

    float tot[2][4][4];   // fp32 total of hH chunks (RN folds)
    float ah[2][4][4];    // per-chunk hH accumulator
    float al[2][4][4];    // persistent scaled-residual accumulator
#pragma unroll
    for (int mt = 0; mt < 2; mt++)
#pragma unroll
        for (int nt = 0; nt < 4; nt++)
#pragma unroll
            for (int e = 0; e < 4; e++) { tot[mt][nt][e] = 0.0f; al[mt][nt][e] = 0.0f; }

    ISSUE_STAGE(0, 0);

    for (int c = 0; c < NCHUNK; ++c) {
        if (c + 1 < NCHUNK) {
            ISSUE_STAGE(c + 1, (c + 1) & 1);
            CP_WAIT1();
        } else {
            CP_WAIT0();
        }
        __syncthreads();

        const uint32_t stA = sb + (c & 1) * STAGE_B;
        const uint32_t stB = stA + BOFF;

        // zero the per-chunk hH accumulator
#pragma unroll
        for (int mt = 0; mt < 2; mt++)
#pragma unroll
            for (int nt = 0; nt < 4; nt++)
#pragma unroll
                for (int e = 0; e < 4; e++) ah[mt][nt][e] = 0.0f;

#pragma unroll
        for (int ks = 0; ks < 4; ++ks) {
            uint32_t a[2][2][4];
            uint32_t b[2][2][4];
#pragma unroll
            for (int s = 0; s < 2; s++) {
#pragma unroll
                for (int mt = 0; mt < 2; mt++) {
                    uint32_t addr = stA + s * ATILE + aRB + mt * 2048 +
                                    (uint32_t)(((aC + 2 * ks) ^ aXor) << 4);
                    LDSM_X4(a[s][mt][0], a[s][mt][1], a[s][mt][2], a[s][mt][3], addr);
                }
#pragma unroll
                for (int np = 0; np < 2; np++) {
                    uint32_t addr = stB + s * BTILE + bRB + np * 2048 +
                                    (uint32_t)(((bC + 2 * ks) ^ bXor) << 4);
                    LDSM_X4(b[s][np][0], b[s][np][1], b[s][np][2], b[s][np][3], addr);
                }
            }
            // p0: h*H -> ah ;  p1: h*M' -> al ;  p2: m'*H -> al
#pragma unroll
            for (int mt = 0; mt < 2; mt++) {
#pragma unroll
                for (int np = 0; np < 2; np++) {
                    MMA16816F16(ah[mt][2 * np + 0], a[0][mt], b[0][np][0], b[0][np][1]);
                    MMA16816F16(ah[mt][2 * np + 1], a[0][mt], b[0][np][2], b[0][np][3]);
                    MMA16816F16(al[mt][2 * np + 0], a[0][mt], b[1][np][0], b[1][np][1]);
                    MMA16816F16(al[mt][2 * np + 1], a[0][mt], b[1][np][2], b[1][np][3]);
                    MMA16816F16(al[mt][2 * np + 0], a[1][mt], b[0][np][0], b[0][np][1]);
                    MMA16816F16(al[mt][2 * np + 1], a[1][mt], b[0][np][2], b[0][np][3]);
                }
            }
        }
        // RN fold of the chunk's hH partial into the fp32 total
#pragma unroll
        for (int mt = 0; mt < 2; mt++)
#pragma unroll
            for (int nt = 0; nt < 4; nt++)
#pragma unroll
                for (int e = 0; e < 4; e++) tot[mt][nt][e] += ah[mt][nt][e];
        __syncthreads();
    }

    // ---- epilogue: tot + al*2^-11 + bias -> sigmoid, float2 stores ----
    const float RS = 1.0f / 2048.0f;
#pragma unroll
    for (int mt = 0; mt < 2; mt++) {
        const int m0 = brow + mg * 32 + mt * 16 + (lane >> 2);
#pragma unroll
        for (int nt = 0; nt < 4; nt++) {
            const int n0 = bcol + ng * 32 + nt * 8 + 2 * (lane & 3);
            const float2 bb = *(const float2*)&bias[n0];
            float2 o0, o1;
            o0.x = sigmoid_acc(fmaf(al[mt][nt][0], RS, tot[mt][nt][0]) + bb.x);
            o0.y = sigmoid_acc(fmaf(al[mt][nt][1], RS, tot[mt][nt][1]) + bb.y);
            o1.x = sigmoid_acc(fmaf(al[mt][nt][2], RS, tot[mt][nt][2]) + bb.x);
            o1.y = sigmoid_acc(fmaf(al[mt][nt][3], RS, tot[mt][nt][3]) + bb.y);
            *(float2*)&S[(size_t)m0 * D_DIM + n0]       = o0;
            *(float2*)&S[(size_t)(m0 + 8) * D_DIM + n0] = o1;
        }
    }
}

// ============================ top-k mask =====================================
// Radix-select, warp-shuffle suffix scans (5 barriers/pass vs 20).
__global__ __launch_bounds__(256)
void topk_mask_kernel(const float* __restrict__ X, const float* __restrict__ S,
                      float* __restrict__ O) {
    const int row = blockIdx.x;
    const int t   = threadIdx.x;
    const int lane = t & 31, wrp = t >> 5;
    const size_t base = (size_t)row * D_DIM;

    const uint4 u = ((const uint4*)(S + base))[t];

    __shared__ int hist[256];
    __shared__ int sscan[256];
    __shared__ int wsum[8];
    __shared__ uint32_t sh_pref;
    __shared__ int sh_need;

    uint32_t prefix = 0;
    int need = K_TOP;
    const uint32_t dmask[4] = {0u, 0xFF000000u, 0xFFFF0000u, 0xFFFFFF00u};

#pragma unroll
    for (int p = 0; p < 4; p++) {
        const int shift = 24 - (p << 3);
        const uint32_t dm = dmask[p];
        hist[t] = 0;
        __syncthreads();
        if ((u.x & dm) == prefix) atomicAdd(&hist[(u.x >> shift) & 255], 1);
        if ((u.y & dm) == prefix) atomicAdd(&hist[(u.y >> shift) & 255], 1);
        if ((u.z & dm) == prefix) atomicAdd(&hist[(u.z >> shift) & 255], 1);
        if ((u.w & dm) == prefix) atomicAdd(&hist[(u.w >> shift) & 255], 1);
        __syncthreads();
        // warp-level inclusive suffix scan of hist (descending index)
        int s = hist[t];
#pragma unroll
        for (int off = 1; off < 32; off <<= 1) {
            int v = __shfl_down_sync(0xffffffffu, s, off);
            if (lane + off < 32) s += v;
        }
        if (lane == 0) wsum[wrp] = s;
        __syncthreads();
        int add = 0;
#pragma unroll
        for (int w2 = 0; w2 < 8; w2++) add += (w2 > wrp) ? wsum[w2] : 0;
        const int ge = s + add;            // # candidates with digit >= t
        sscan[t] = ge;
        __syncthreads();
        const int nxt = (t < 255) ? sscan[t + 1] : 0;
        if (ge >= need && nxt < need) {
            sh_pref = prefix | ((uint32_t)t << shift);
            sh_need = need - nxt;
        }
        __syncthreads();
        prefix = sh_pref;
        need   = sh_need;
        __syncthreads();
    }

    const uint32_t T = prefix;  // exact K-th largest bit pattern

    // index-ordered rank among elements == T (lowest-index tie-break)
    const int e0 = (u.x == T), e1 = (u.y == T), e2 = (u.z == T), e3 = (u.w == T);
    const int cnt = e0 + e1 + e2 + e3;
    int incl = cnt;
#pragma unroll
    for (int off = 1; off < 32; off <<= 1) {
        int v = __shfl_up_sync(0xffffffffu, incl, off);
        if (lane >= off) incl += v;
    }
    if (lane == 31) wsum[wrp] = incl;
    __syncthreads();
    if (t == 0) {
        int ssum = 0;
#pragma unroll
        for (int i = 0; i < 8; i++) { int v = wsum[i]; wsum[i] = ssum; ssum += v; }
    }
    __syncthreads();
    int rank = wsum[wrp] + (incl - cnt);

    const float4 xv = ((const float4*)(X + base))[t];
    float4 o;
    const bool s0 = (u.x > T) || (e0 && rank < need); rank += e0;
    const bool s1 = (u.y > T) || (e1 && rank < need); rank += e1;
    const bool s2 = (u.z > T) || (e2 && rank < need); rank += e2;
    const bool s3 = (u.w > T) || (e3 && rank < need);
    o.x = s0 ? xv.x : 0.0f;
    o.y = s1 ? xv.y : 0.0f;
    o.z = s2 ? xv.z : 0.0f;
    o.w = s3 ? xv.w : 0.0f;
    ((float4*)(O + base))[t] = o;
}

// ============================ launch =========================================
extern "C" void kernel_launch(void* const* d_in, const int* in_sizes, int n_in,
                              void* d_out, int out_size) {
    const float* X = (const float*)d_in[0];  // [N, 1024]
    const float* W = (const float*)d_in[1];  // [1024, 1024]
    const float* b = (const float*)d_in[2];  // [1024]
    float* out = (float*)d_out;              // [2, N, 1024]

    const int N = in_sizes[0] / D_DIM;
    float* S = out + (size_t)N * D_DIM;

    uint16_t *wh, *wm, *xh, *xm;
    cudaGetSymbolAddress((void**)&wh, g_Wh);
    cudaGetSymbolAddress((void**)&wm, g_Wm);
    cudaGetSymbolAddress((void**)&xh, g_Xh);
    cudaGetSymbolAddress((void**)&xm, g_Xm);

    cudaFuncSetAttribute(gemm_hmma_kernel,
                         cudaFuncAttributeMaxDynamicSharedMemorySize, SMEM_GEMM);

    split2_kernel<<<D_DIM * D_DIM / 8 / 256, 256>>>(W, wh, wm);
    split2_kernel<<<(int)((size_t)N * D_DIM / 8 / 256), 256>>>(X, xh, xm);
    gemm_hmma_kernel<<<dim3(D_DIM / 128, N / 64), 256, SMEM_GEMM>>>(b, S);
    topk_mask_kernel<<<N, 256>>>(X, S, out);
}

// round 11
// speedup vs baseline: 1.9200x; 1.0296x over previous
#include <cuda_runtime.h>
#include <cuda_fp16.h>
#include <cstdint>

#define D_DIM 1024
#define K_TOP 307
#define MAX_N 65536

// ============================ PTX helpers ===================================
__device__ __forceinline__ uint32_t smem_u32(const void* p) {
    uint32_t a;
    asm("{ .reg .u64 t; cvta.to.shared.u64 t, %1; cvt.u32.u64 %0, t; }" : "=r"(a) : "l"(p));
    return a;
}
#define CPA16(saddr, gptr) \
    asm volatile("cp.async.cg.shared.global [%0], [%1], 16;" :: "r"(saddr), "l"(gptr) : "memory")
#define CP_COMMIT() asm volatile("cp.async.commit_group;" ::: "memory")
#define CP_WAIT1()  asm volatile("cp.async.wait_group 1;" ::: "memory")
#define CP_WAIT0()  asm volatile("cp.async.wait_group 0;" ::: "memory")

#define LDSM_X4(r0, r1, r2, r3, addr) \
    asm volatile("ldmatrix.sync.aligned.m8n8.x4.shared.b16 {%0,%1,%2,%3}, [%4];" \
        : "=r"(r0), "=r"(r1), "=r"(r2), "=r"(r3) : "r"(addr))

#define MMA16816F16(d, a, b0, b1) \
    asm volatile("mma.sync.aligned.m16n8k16.row.col.f32.f16.f16.f32 " \
        "{%0,%1,%2,%3}, {%4,%5,%6,%7}, {%8,%9}, {%0,%1,%2,%3};" \
        : "+f"((d)[0]), "+f"((d)[1]), "+f"((d)[2]), "+f"((d)[3]) \
        : "r"((a)[0]), "r"((a)[1]), "r"((a)[2]), "r"((a)[3]), "r"(b0), "r"(b1))

// ============================ numeric helpers ================================
__device__ __forceinline__ float sigmoid_acc(float z) {
    float x = -z;
    x = fminf(fmaxf(x, -87.0f), 87.0f);
    float t = x * 1.4426950408889634f;
    float n = rintf(t);
    float r = fmaf(n, -0.693145751953125f, x);
    r = fmaf(n, -1.42860676533018687e-06f, r);
    float p = 1.9875691500e-4f;
    p = fmaf(p, r, 1.3981999507e-3f);
    p = fmaf(p, r, 8.3333331174e-3f);
    p = fmaf(p, r, 4.1665795894e-2f);
    p = fmaf(p, r, 1.6666665459e-1f);
    p = fmaf(p, r, 5.0000001201e-1f);
    float y = fmaf(r * r, p, r) + 1.0f;
    int   i  = (int)n;
    float sc = __int_as_float((i + 127) << 23);
    return 1.0f / (1.0f + y * sc);
}

// fp16 2-way split: x = h + m * 2^-11  (m stored pre-scaled by 2048, normal range)
__device__ __forceinline__ void split2h(float x, uint16_t& h, uint16_t& m) {
    __half hh = __float2half_rn(x);
    float  hf = __half2float(hh);
    __half mh = __float2half_rn((x - hf) * 2048.0f);
    h = __half_as_ushort(hh);
    m = __half_as_ushort(mh);
}

// ============================ pre-split storage ==============================
__device__ __align__(16) uint16_t g_Wh[D_DIM * D_DIM];
__device__ __align__(16) uint16_t g_Wm[D_DIM * D_DIM];
__device__ __align__(16) uint16_t g_Xh[(size_t)MAX_N * D_DIM];
__device__ __align__(16) uint16_t g_Xm[(size_t)MAX_N * D_DIM];

__global__ __launch_bounds__(256)
void split2_kernel(const float* __restrict__ src, uint16_t* __restrict__ oh,
                   uint16_t* __restrict__ om) {
    size_t gid = (size_t)blockIdx.x * 256 + threadIdx.x;  // one 8-float group
    float4 a = ((const float4*)src)[2 * gid];
    float4 c = ((const float4*)src)[2 * gid + 1];
    float v[8] = {a.x, a.y, a.z, a.w, c.x, c.y, c.z, c.w};
    uint16_t h[8], m[8];
#pragma unroll
    for (int i = 0; i < 8; i++) split2h(v[i], h[i], m[i]);
    uint4 H = {(uint32_t)h[0] | ((uint32_t)h[1] << 16), (uint32_t)h[2] | ((uint32_t)h[3] << 16),
               (uint32_t)h[4] | ((uint32_t)h[5] << 16), (uint32_t)h[6] | ((uint32_t)h[7] << 16)};
    uint4 M = {(uint32_t)m[0] | ((uint32_t)m[1] << 16), (uint32_t)m[2] | ((uint32_t)m[3] << 16),
               (uint32_t)m[4] | ((uint32_t)m[5] << 16), (uint32_t)m[6] | ((uint32_t)m[7] << 16)};
    ((uint4*)oh)[gid] = H;
    ((uint4*)om)[gid] = M;
}

// ============================ GEMM (HMMA fp16 mma.sync) ======================
// CTA tile 64(M) x 128(N), K chunks of 64. 3 fp16 products, p-OUTER ordering:
//   hH -> per-chunk accumulator ah (zeroed each chunk, RN-folded into tot)
//   hM' then m'H -> persistent accumulator al (dependent writes 8 MMAs apart)
#define ATILE   8192                    // 64 x 64 fp16
#define BTILE   16384                   // 128 x 64 fp16
#define BOFF    (2 * ATILE)             // 16384
#define STAGE_B (2 * ATILE + 2 * BTILE) // 49152
#define SMEM_GEMM (2 * STAGE_B)         // 98304
#define NCHUNK  (D_DIM / 64)            // 16

__global__ __launch_bounds__(256, 1)
void gemm_hmma_kernel(const float* __restrict__ bias, float* __restrict__ S) {
    extern __shared__ char smem[];
    const uint32_t sb = smem_u32(smem);
    const int tid  = threadIdx.x;
    const int lane = tid & 31;
    const int wid  = tid >> 5;
    const int mg   = wid >> 2;          // 0..1 : rows mg*32..+32
    const int ng   = wid & 3;           // 0..3 : cols ng*32..+32
    const int brow = blockIdx.y << 6;   // 64-row tile
    const int bcol = blockIdx.x << 7;   // 128-col tile

#define ISSUE_STAGE(c, s)                                                     \
    do {                                                                      \
        const int k0_ = (c) * 64;                                             \
        const uint32_t st_ = sb + (s) * STAGE_B;                              \
        _Pragma("unroll")                                                     \
        for (int j = 0; j < 2; j++) {                                         \
            int g = tid + j * 256;                                            \
            int row = g >> 3, cc = g & 7;                                     \
            uint32_t sw = (uint32_t)(row * 128 + ((cc ^ (row & 7)) << 4));    \
            size_t ga = (size_t)(brow + row) * D_DIM + k0_ + cc * 8;          \
            CPA16(st_ + 0 * ATILE + sw, g_Xh + ga);                           \
            CPA16(st_ + 1 * ATILE + sw, g_Xm + ga);                           \
        }                                                                     \
        _Pragma("unroll")                                                     \
        for (int j = 0; j < 4; j++) {                                         \
            int g = tid + j * 256;                                            \
            int row = g >> 3, cc = g & 7;                                     \
            uint32_t sw = (uint32_t)(row * 128 + ((cc ^ (row & 7)) << 4));    \
            size_t gb = (size_t)(bcol + row) * D_DIM + k0_ + cc * 8;          \
            CPA16(st_ + BOFF + 0 * BTILE + sw, g_Wh + gb);                    \
            CPA16(st_ + BOFF + 1 * BTILE + sw, g_Wm + gb);                    \
        }                                                                     \
        CP_COMMIT();                                                          \
    } while (0)

    // ---- ldmatrix lane addressing (validated in rounds 8-10) ----
    const int aRow = mg * 32 + (((lane >> 3) & 1) << 3) + (lane & 7);   // <64
    const int aC   = (lane >> 4);
    const uint32_t aRB = (uint32_t)(aRow * 128);
    const int aXor = aRow & 7;
    const int bRow = ng * 32 + (((lane >> 4) & 1) << 3) + (lane & 7);   // <128
    const int bC   = (lane >> 3) & 1;
    const uint32_t bRB = (uint32_t)(bRow * 128);
    const int bXor = bRow & 7;

    float tot[2][4][4];   // fp32 total of hH chunks (RN folds)
    float ah[2][4][4];    // per-chunk hH accumulator
    float al[2][4][4];    // persistent scaled-residual accumulator
#pragma unroll
    for (int mt = 0; mt < 2; mt++)
#pragma unroll
        for (int nt = 0; nt < 4; nt++)
#pragma unroll
            for (int e = 0; e < 4; e++) { tot[mt][nt][e] = 0.0f; al[mt][nt][e] = 0.0f; }

    ISSUE_STAGE(0, 0);

    for (int c = 0; c < NCHUNK; ++c) {
        if (c + 1 < NCHUNK) {
            ISSUE_STAGE(c + 1, (c + 1) & 1);
            CP_WAIT1();
        } else {
            CP_WAIT0();
        }
        __syncthreads();

        const uint32_t stA = sb + (c & 1) * STAGE_B;
        const uint32_t stB = stA + BOFF;

        // zero the per-chunk hH accumulator
#pragma unroll
        for (int mt = 0; mt < 2; mt++)
#pragma unroll
            for (int nt = 0; nt < 4; nt++)
#pragma unroll
                for (int e = 0; e < 4; e++) ah[mt][nt][e] = 0.0f;

#pragma unroll
        for (int ks = 0; ks < 4; ++ks) {
            uint32_t a[2][2][4];
            uint32_t b[2][2][4];
#pragma unroll
            for (int s = 0; s < 2; s++) {
#pragma unroll
                for (int mt = 0; mt < 2; mt++) {
                    uint32_t addr = stA + s * ATILE + aRB + mt * 2048 +
                                    (uint32_t)(((aC + 2 * ks) ^ aXor) << 4);
                    LDSM_X4(a[s][mt][0], a[s][mt][1], a[s][mt][2], a[s][mt][3], addr);
                }
#pragma unroll
                for (int np = 0; np < 2; np++) {
                    uint32_t addr = stB + s * BTILE + bRB + np * 2048 +
                                    (uint32_t)(((bC + 2 * ks) ^ bXor) << 4);
                    LDSM_X4(b[s][np][0], b[s][np][1], b[s][np][2], b[s][np][3], addr);
                }
            }
            // p0: h*H -> ah (8 MMAs, independent)
#pragma unroll
            for (int mt = 0; mt < 2; mt++)
#pragma unroll
                for (int np = 0; np < 2; np++) {
                    MMA16816F16(ah[mt][2 * np + 0], a[0][mt], b[0][np][0], b[0][np][1]);
                    MMA16816F16(ah[mt][2 * np + 1], a[0][mt], b[0][np][2], b[0][np][3]);
                }
            // p1: h*M' -> al (8 MMAs)
#pragma unroll
            for (int mt = 0; mt < 2; mt++)
#pragma unroll
                for (int np = 0; np < 2; np++) {
                    MMA16816F16(al[mt][2 * np + 0], a[0][mt], b[1][np][0], b[1][np][1]);
                    MMA16816F16(al[mt][2 * np + 1], a[0][mt], b[1][np][2], b[1][np][3]);
                }
            // p2: m'*H -> al (8 MMAs; dependent write 8 MMAs after its p1 pair)
#pragma unroll
            for (int mt = 0; mt < 2; mt++)
#pragma unroll
                for (int np = 0; np < 2; np++) {
                    MMA16816F16(al[mt][2 * np + 0], a[1][mt], b[0][np][0], b[0][np][1]);
                    MMA16816F16(al[mt][2 * np + 1], a[1][mt], b[0][np][2], b[0][np][3]);
                }
        }
        // RN fold of the chunk's hH partial into the fp32 total
#pragma unroll
        for (int mt = 0; mt < 2; mt++)
#pragma unroll
            for (int nt = 0; nt < 4; nt++)
#pragma unroll
                for (int e = 0; e < 4; e++) tot[mt][nt][e] += ah[mt][nt][e];
        __syncthreads();
    }

    // ---- epilogue: tot + al*2^-11 + bias -> sigmoid, float2 stores ----
    const float RS = 1.0f / 2048.0f;
#pragma unroll
    for (int mt = 0; mt < 2; mt++) {
        const int m0 = brow + mg * 32 + mt * 16 + (lane >> 2);
#pragma unroll
        for (int nt = 0; nt < 4; nt++) {
            const int n0 = bcol + ng * 32 + nt * 8 + 2 * (lane & 3);
            const float2 bb = *(const float2*)&bias[n0];
            float2 o0, o1;
            o0.x = sigmoid_acc(fmaf(al[mt][nt][0], RS, tot[mt][nt][0]) + bb.x);
            o0.y = sigmoid_acc(fmaf(al[mt][nt][1], RS, tot[mt][nt][1]) + bb.y);
            o1.x = sigmoid_acc(fmaf(al[mt][nt][2], RS, tot[mt][nt][2]) + bb.x);
            o1.y = sigmoid_acc(fmaf(al[mt][nt][3], RS, tot[mt][nt][3]) + bb.y);
            *(float2*)&S[(size_t)m0 * D_DIM + n0]       = o0;
            *(float2*)&S[(size_t)(m0 + 8) * D_DIM + n0] = o1;
        }
    }
}

// ============================ top-k mask =====================================
// 2 radix passes (16-bit prefix) + gather tie-class candidates (avg ~4) +
// exact (value desc, index asc) ranking on a selection bitmap.
// Fallback to 2 more radix passes if tie-class > 64 (pathological).
__global__ __launch_bounds__(256)
void topk_mask_kernel(const float* __restrict__ X, const float* __restrict__ S,
                      float* __restrict__ O) {
    const int row = blockIdx.x;
    const int t   = threadIdx.x;
    const int lane = t & 31, wrp = t >> 5;
    const size_t base = (size_t)row * D_DIM;

    const uint4 u = ((const uint4*)(S + base))[t];

    __shared__ int hist[256];
    __shared__ int sscan[256];
    __shared__ int wsum[8];
    __shared__ uint32_t sh_pref;
    __shared__ int sh_need;
    __shared__ int ccount;
    __shared__ uint32_t candv[64];
    __shared__ uint16_t candi[64];
    __shared__ uint32_t selbmp[32];

    uint32_t prefix = 0;
    int need = K_TOP;

#pragma unroll
    for (int p = 0; p < 2; p++) {
        const int shift = 24 - (p << 3);
        const uint32_t dm = (p == 0) ? 0u : 0xFF000000u;
        hist[t] = 0;
        __syncthreads();
        if ((u.x & dm) == prefix) atomicAdd(&hist[(u.x >> shift) & 255], 1);
        if ((u.y & dm) == prefix) atomicAdd(&hist[(u.y >> shift) & 255], 1);
        if ((u.z & dm) == prefix) atomicAdd(&hist[(u.z >> shift) & 255], 1);
        if ((u.w & dm) == prefix) atomicAdd(&hist[(u.w >> shift) & 255], 1);
        __syncthreads();
        int s = hist[t];
#pragma unroll
        for (int off = 1; off < 32; off <<= 1) {
            int v = __shfl_down_sync(0xffffffffu, s, off);
            if (lane + off < 32) s += v;
        }
        if (lane == 0) wsum[wrp] = s;
        __syncthreads();
        int add = 0;
#pragma unroll
        for (int w2 = 0; w2 < 8; w2++) add += (w2 > wrp) ? wsum[w2] : 0;
        const int ge = s + add;
        sscan[t] = ge;
        __syncthreads();
        const int nxt = (t < 255) ? sscan[t + 1] : 0;
        if (ge >= need && nxt < need) {
            sh_pref = prefix | ((uint32_t)t << shift);
            sh_need = need - nxt;
        }
        __syncthreads();
        prefix = sh_pref;
        need   = sh_need;
    }

    // ---- gather tie-class candidates (top16 == prefix bits) ----
    if (t == 0) ccount = 0;
    if (t < 32) selbmp[t] = 0;
    __syncthreads();
    const uint32_t p16 = prefix;            // bits[31:16] of K-th value, low 16 = 0
    const int idx0 = t << 2;
    {
        const uint32_t vv[4] = {u.x, u.y, u.z, u.w};
#pragma unroll
        for (int k = 0; k < 4; k++) {
            if ((vv[k] & 0xFFFF0000u) == p16) {
                int pos = atomicAdd(&ccount, 1);
                if (pos < 64) { candv[pos] = vv[k]; candi[pos] = (uint16_t)(idx0 + k); }
            }
        }
    }
    __syncthreads();
    const int cnt = ccount;

    const float4 xv = ((const float4*)(X + base))[t];
    float4 o;

    if (cnt <= 64) {
        // rank candidates exactly: value desc, index asc; select rank < need
        if (t < cnt) {
            const uint32_t v = candv[t];
            const uint32_t idx = candi[t];
            int r = 0;
            for (int j = 0; j < cnt; j++) {
                const uint32_t vj = candv[j];
                r += (vj > v) || (vj == v && candi[j] < idx);
            }
            if (r < need) atomicOr(&selbmp[idx >> 5], 1u << (idx & 31));
        }
        __syncthreads();
        const uint32_t h0 = u.x & 0xFFFF0000u, h1 = u.y & 0xFFFF0000u;
        const uint32_t h2 = u.z & 0xFFFF0000u, h3 = u.w & 0xFFFF0000u;
        const bool s0 = (h0 > p16) || (h0 == p16 && ((selbmp[(idx0 + 0) >> 5] >> ((idx0 + 0) & 31)) & 1u));
        const bool s1 = (h1 > p16) || (h1 == p16 && ((selbmp[(idx0 + 1) >> 5] >> ((idx0 + 1) & 31)) & 1u));
        const bool s2 = (h2 > p16) || (h2 == p16 && ((selbmp[(idx0 + 2) >> 5] >> ((idx0 + 2) & 31)) & 1u));
        const bool s3 = (h3 > p16) || (h3 == p16 && ((selbmp[(idx0 + 3) >> 5] >> ((idx0 + 3) & 31)) & 1u));
        o.x = s0 ? xv.x : 0.0f;
        o.y = s1 ? xv.y : 0.0f;
        o.z = s2 ? xv.z : 0.0f;
        o.w = s3 ? xv.w : 0.0f;
    } else {
        // ---- fallback: finish radix passes 2,3 then rank ties (rare) ----
        __syncthreads();
#pragma unroll
        for (int p = 2; p < 4; p++) {
            const int shift = 24 - (p << 3);
            const uint32_t dm = (p == 2) ? 0xFFFF0000u : 0xFFFFFF00u;
            hist[t] = 0;
            __syncthreads();
            if ((u.x & dm) == prefix) atomicAdd(&hist[(u.x >> shift) & 255], 1);
            if ((u.y & dm) == prefix) atomicAdd(&hist[(u.y >> shift) & 255], 1);
            if ((u.z & dm) == prefix) atomicAdd(&hist[(u.z >> shift) & 255], 1);
            if ((u.w & dm) == prefix) atomicAdd(&hist[(u.w >> shift) & 255], 1);
            __syncthreads();
            int s = hist[t];
#pragma unroll
            for (int off = 1; off < 32; off <<= 1) {
                int v = __shfl_down_sync(0xffffffffu, s, off);
                if (lane + off < 32) s += v;
            }
            if (lane == 0) wsum[wrp] = s;
            __syncthreads();
            int add = 0;
#pragma unroll
            for (int w2 = 0; w2 < 8; w2++) add += (w2 > wrp) ? wsum[w2] : 0;
            const int ge = s + add;
            sscan[t] = ge;
            __syncthreads();
            const int nxt = (t < 255) ? sscan[t + 1] : 0;
            if (ge >= need && nxt < need) {
                sh_pref = prefix | ((uint32_t)t << shift);
                sh_need = need - nxt;
            }
            __syncthreads();
            prefix = sh_pref;
            need   = sh_need;
            __syncthreads();
        }
        const uint32_t T = prefix;
        const int e0 = (u.x == T), e1 = (u.y == T), e2 = (u.z == T), e3 = (u.w == T);
        const int cnt4 = e0 + e1 + e2 + e3;
        int incl = cnt4;
#pragma unroll
        for (int off = 1; off < 32; off <<= 1) {
            int v = __shfl_up_sync(0xffffffffu, incl, off);
            if (lane >= off) incl += v;
        }
        if (lane == 31) wsum[wrp] = incl;
        __syncthreads();
        if (t == 0) {
            int ssum = 0;
#pragma unroll
            for (int i = 0; i < 8; i++) { int v = wsum[i]; wsum[i] = ssum; ssum += v; }
        }
        __syncthreads();
        int rank = wsum[wrp] + (incl - cnt4);
        const bool s0 = (u.x > T) || (e0 && rank < need); rank += e0;
        const bool s1 = (u.y > T) || (e1 && rank < need); rank += e1;
        const bool s2 = (u.z > T) || (e2 && rank < need); rank += e2;
        const bool s3 = (u.w > T) || (e3 && rank < need);
        o.x = s0 ? xv.x : 0.0f;
        o.y = s1 ? xv.y : 0.0f;
        o.z = s2 ? xv.z : 0.0f;
        o.w = s3 ? xv.w : 0.0f;
    }
    ((float4*)(O + base))[t] = o;
}

// ============================ launch =========================================
extern "C" void kernel_launch(void* const* d_in, const int* in_sizes, int n_in,
                              void* d_out, int out_size) {
    const float* X = (const float*)d_in[0];  // [N, 1024]
    const float* W = (const float*)d_in[1];  // [1024, 1024]
    const float* b = (const float*)d_in[2];  // [1024]
    float* out = (float*)d_out;              // [2, N, 1024]

    const int N = in_sizes[0] / D_DIM;
    float* S = out + (size_t)N * D_DIM;

    uint16_t *wh, *wm, *xh, *xm;
    cudaGetSymbolAddress((void**)&wh, g_Wh);
    cudaGetSymbolAddress((void**)&wm, g_Wm);
    cudaGetSymbolAddress((void**)&xh, g_Xh);
    cudaGetSymbolAddress((void**)&xm, g_Xm);

    cudaFuncSetAttribute(gemm_hmma_kernel,
                         cudaFuncAttributeMaxDynamicSharedMemorySize, SMEM_GEMM);

    split2_kernel<<<D_DIM * D_DIM / 8 / 256, 256>>>(W, wh, wm);
    split2_kernel<<<(int)((size_t)N * D_DIM / 8 / 256), 256>>>(X, xh, xm);
    gemm_hmma_kernel<<<dim3(D_DIM / 128, N / 64), 256, SMEM_GEMM>>>(b, S);
    topk_mask_kernel<<<N, 256>>>(X, S, out);
}